// round 5
// baseline (speedup 1.0000x reference)
#include <cuda_runtime.h>

#define Nq 32768
#define Mp 8192
#define C  128

// ---- knn config ----
#define KTPB 128            // threads per knn block
#define KQB  128            // queries per block (QPT=1)
#define NCH  4              // candidate quarters
#define KHALF (Mp/NCH)      // 2048 candidates per chunk
#define SUB  512            // pairs per smem sub-chunk (16KB)
#define NSUB (KHALF/2/SUB)  // 2 sub-chunks per chunk

typedef unsigned long long ull;

union F2U { float2 f; ull u; };
__device__ __forceinline__ ull pk2(float a, float b){ F2U t; t.f.x=a; t.f.y=b; return t.u; }
__device__ __forceinline__ float lo2(ull v){ F2U t; t.u=v; return t.f.x; }
__device__ __forceinline__ float hi2(ull v){ F2U t; t.u=v; return t.f.y; }
__device__ __forceinline__ ull fma2(ull a, ull b, ull c){
    ull d; asm("fma.rn.f32x2 %0, %1, %2, %3;" : "=l"(d) : "l"(a), "l"(b), "l"(c)); return d;
}
__device__ __forceinline__ ull add2(ull a, ull b){
    ull d; asm("add.rn.f32x2 %0, %1, %2;" : "=l"(d) : "l"(a), "l"(b)); return d;
}

// branchless stable top-3 insert (strict <  => ties keep earlier/lower index)
__device__ __forceinline__ void ins3(float t, int idx,
                                     float& d0, float& d1, float& d2,
                                     int& i0, int& i1, int& i2)
{
    const bool c0 = t < d0, c1 = t < d1, c2 = t < d2;
    d2 = c1 ? d1 : (c2 ? t : d2);
    i2 = c1 ? i1 : (c2 ? idx : i2);
    d1 = c0 ? d0 : (c1 ? t : d1);
    i1 = c0 ? i0 : (c1 ? idx : i1);
    d0 = c0 ? t : d0;
    i0 = c0 ? idx : i0;
}

// ---------------- scratch (device globals; no allocs allowed) ----------------
__device__ float4 g_wq[Nq];
__device__ int4   g_iq[Nq];
__device__ float4 g_pd[NCH*Nq];
__device__ int4   g_pi[NCH*Nq];
__device__ float  g_x0[Nq*C];
__device__ float  g_ya[Nq*C];
__device__ float  g_yb[Nq*C];
__device__ float  g_wt[3*C*C];
__device__ float  g_sum[C];
__device__ float  g_sq[C];
__device__ unsigned g_ctr;
__device__ float  g_ab[2*C];

extern __shared__ unsigned char s_raw[];

// ---------------- W transpose x3 in one launch ----------------
__global__ void __launch_bounds__(256,1) transpose3_kernel(const float* __restrict__ w0,
                                                           const float* __restrict__ w1,
                                                           const float* __restrict__ w2,
                                                           float* __restrict__ wt)
{
    const int b = blockIdx.x;                  // 192 blocks
    const float* w = (b < 64) ? w0 : ((b < 128) ? w1 : w2);
    const int local = (b & 63)*256 + threadIdx.x;   // 0..16383
    wt[(b >> 6)*16384 + local] = w[(local & 127)*128 + (local >> 7)];
}

// -------- kNN partial: QPT=1, streamed smem sub-chunks, branchless insert --------
__global__ void __launch_bounds__(KTPB,8) knn_part_kernel(const float* __restrict__ pos1,
                                                          const float* __restrict__ pos2,
                                                          float4* __restrict__ pd,
                                                          int4*  __restrict__ pi)
{
    __shared__ ulonglong2 sA[SUB];   // (.x = x-pair, .y = y-pair) of (-2x)
    __shared__ ulonglong2 sB[SUB];   // (.x = z-pair, .y = n2-pair)
    const int t     = threadIdx.x;
    const int chunk = blockIdx.x & (NCH-1);
    const int n     = (blockIdx.x >> 2) * KQB + t;   // this thread's query

    const float px = pos1[3*n], py = pos1[3*n+1], pz = pos1[3*n+2];
    const ull pxx = pk2(px,px), pyy = pk2(py,py), pzz = pk2(pz,pz);

    float d0=3.4e38f, d1=3.4e38f, d2=3.4e38f;
    int   i0=0, i1=0, i2=0;

    const int pb0 = chunk * (KHALF/2);   // base pair index for this chunk

    for (int sc = 0; sc < NSUB; sc++){
        const int pb = pb0 + sc*SUB;
        __syncthreads();
        #pragma unroll
        for (int i = 0; i < SUB/KTPB; i++){          // 4 pair-loads per thread
            const int p = t + i*KTPB;
            const float2* q2 = (const float2*)(pos2 + 6*(pb + p));
            const float2 a = q2[0], b = q2[1], c = q2[2];
            const float x0=a.x, y0=a.y, z0=b.x, x1=b.y, y1=c.x, z1=c.y;
            const float n0 = x0*x0 + y0*y0 + z0*z0;
            const float n1 = x1*x1 + y1*y1 + z1*z1;
            ulonglong2 A, B;
            A.x = pk2(-2.f*x0, -2.f*x1);
            A.y = pk2(-2.f*y0, -2.f*y1);
            B.x = pk2(-2.f*z0, -2.f*z1);
            B.y = pk2(n0, n1);
            sA[p] = A; sB[p] = B;
        }
        __syncthreads();

        #pragma unroll 4
        for (int p = 0; p < SUB; p++){
            const ulonglong2 A = sA[p];
            const ulonglong2 B = sB[p];
            ull tt = fma2(pzz, B.x, B.y);
            tt = fma2(pyy, A.y, tt);
            tt = fma2(pxx, A.x, tt);
            const float tl = lo2(tt), th = hi2(tt);
            if (fminf(tl, th) < d2){
                const int g = 2*(pb + p);
                ins3(tl, g,   d0, d1, d2, i0, i1, i2);
                ins3(th, g+1, d0, d1, d2, i0, i1, i2);
            }
        }
    }

    pd[chunk*Nq + n] = make_float4(d0, d1, d2, 0.f);
    pi[chunk*Nq + n] = make_int4(i0, i1, i2, 0);
}

// ---------------- merge partials -> weights/indices ----------------
__global__ void __launch_bounds__(256,1) knn_merge_kernel(const float* __restrict__ pos1,
                                                          const float4* __restrict__ pd,
                                                          const int4*  __restrict__ pi,
                                                          float4* __restrict__ wq,
                                                          int4*  __restrict__ iq)
{
    const int n = blockIdx.x*256 + threadIdx.x;
    float4 v = pd[n];
    int4  id = pi[n];
    float d0=v.x, d1=v.y, d2=v.z;
    int   i0=id.x, i1=id.y, i2=id.z;

    #pragma unroll
    for (int c = 1; c < NCH; c++){
        const float4 e = pd[c*Nq + n];
        const int4   j = pi[c*Nq + n];
        ins3(e.x, j.x, d0, d1, d2, i0, i1, i2);
        ins3(e.y, j.y, d0, d1, d2, i0, i1, i2);
        ins3(e.z, j.z, d0, d1, d2, i0, i1, i2);
    }

    const float px = pos1[3*n], py = pos1[3*n+1], pz = pos1[3*n+2];
    const float n1 = px*px + py*py + pz*pz;
    const float a0 = fmaxf(d0 + n1, 0.f) + 1e-8f;
    const float a1 = fmaxf(d1 + n1, 0.f) + 1e-8f;
    const float a2 = fmaxf(d2 + n1, 0.f) + 1e-8f;
    const float w0 = 1.f/a0, w1 = 1.f/a1, w2 = 1.f/a2;
    const float inv = 1.f/(w0 + w1 + w2);
    wq[n] = make_float4(w0*inv, w1*inv, w2*inv, 0.f);
    iq[n] = make_int4(i0, i1, i2, 0);
}

// ---------------- interpolation: warp per point ----------------
__global__ void __launch_bounds__(256,1) interp_kernel(const float* __restrict__ feat2,
                                                       const float4* __restrict__ wq,
                                                       const int4*  __restrict__ iq,
                                                       float* __restrict__ x0)
{
    const int gw   = (blockIdx.x*256 + threadIdx.x) >> 5;
    const int lane = threadIdx.x & 31;
    const int4   id = iq[gw];
    const float4 w  = wq[gw];
    const float4* f4 = (const float4*)feat2;
    const float4 a = f4[id.x*32 + lane];
    const float4 b = f4[id.y*32 + lane];
    const float4 c = f4[id.z*32 + lane];
    float4 o;
    o.x = a.x*w.x + b.x*w.y + c.x*w.z;
    o.y = a.y*w.x + b.y*w.y + c.y*w.z;
    o.z = a.z*w.x + b.z*w.y + c.z*w.z;
    o.w = a.w*w.x + b.w*w.y + c.w*w.z;
    ((float4*)x0)[gw*32 + lane] = o;
}

// -- fused GEMM (+prev BN/ReLU on load) + BN-stat accumulation + last-block stats --
// 64-row x 128-col tile, 256 threads, 4x8 micro-tile, grid=512 (2 CTAs/SM)
__global__ void __launch_bounds__(256,2) gemm_bn_kernel(const float* __restrict__ x,
                                                        const float* __restrict__ wt,   // [k][j]
                                                        const float* __restrict__ bias,
                                                        const float* __restrict__ abin, // prev scale|shift or null
                                                        const float* __restrict__ g,
                                                        const float* __restrict__ be,
                                                        float* __restrict__ y,
                                                        float* __restrict__ gs,
                                                        float* __restrict__ gq,
                                                        unsigned* __restrict__ ctr,
                                                        float* __restrict__ about)
{
    float* Xs = (float*)s_raw;        // [64][132]
    float* Ws = Xs + 64*132;          // [128][128]
    const int t   = threadIdx.x;
    const int blk = blockIdx.x;

    {   // load W tile (pre-transposed)
        const float4* wt4 = (const float4*)wt;
        float4* ws4 = (float4*)Ws;
        #pragma unroll
        for (int i = 0; i < 16; i++) ws4[i*256 + t] = wt4[i*256 + t];
    }
    {   // load X tile (64 rows) with fused affine+relu
        const int lane = t & 31;
        const int rg   = t >> 5;      // 0..7
        float4 sc, sf;
        const bool aff = (abin != 0);
        if (aff){ sc = ((const float4*)abin)[lane]; sf = ((const float4*)abin)[32 + lane]; }
        const float4* x4 = (const float4*)x + (size_t)blk*(64*32);
        #pragma unroll
        for (int i = 0; i < 8; i++){
            const int r = rg + i*8;
            float4 v = x4[r*32 + lane];
            if (aff){
                v.x = fmaxf(fmaf(v.x, sc.x, sf.x), 0.f);
                v.y = fmaxf(fmaf(v.y, sc.y, sf.y), 0.f);
                v.z = fmaxf(fmaf(v.z, sc.z, sf.z), 0.f);
                v.w = fmaxf(fmaf(v.w, sc.w, sf.w), 0.f);
            }
            *(float4*)(Xs + r*132 + lane*4) = v;
        }
    }
    __syncthreads();

    const int tc = t & 15, tr = t >> 4;     // 16 col-groups x 16 row-groups
    const int rbase = tr*4, cbase = tc*8;

    ull acc[4][4];
    {
        const ull b0 = pk2(bias[cbase+0], bias[cbase+1]);
        const ull b1 = pk2(bias[cbase+2], bias[cbase+3]);
        const ull b2 = pk2(bias[cbase+4], bias[cbase+5]);
        const ull b3 = pk2(bias[cbase+6], bias[cbase+7]);
        #pragma unroll
        for (int r = 0; r < 4; r++){ acc[r][0]=b0; acc[r][1]=b1; acc[r][2]=b2; acc[r][3]=b3; }
    }

    const float* xrow = Xs + rbase*132;
    #pragma unroll 2
    for (int k4 = 0; k4 < 32; k4++){
        const int k = k4*4;
        float4 xv[4];
        #pragma unroll
        for (int r = 0; r < 4; r++) xv[r] = *(const float4*)(xrow + r*132 + k);
        #pragma unroll
        for (int kk = 0; kk < 4; kk++){
            const float4 wa = *(const float4*)(Ws + (k+kk)*128 + cbase);
            const float4 wb = *(const float4*)(Ws + (k+kk)*128 + cbase + 4);
            const ull w0 = pk2(wa.x, wa.y), w1 = pk2(wa.z, wa.w);
            const ull w2 = pk2(wb.x, wb.y), w3 = pk2(wb.z, wb.w);
            #pragma unroll
            for (int r = 0; r < 4; r++){
                const float xvr = ((const float*)&xv[r])[kk];
                const ull xd = pk2(xvr, xvr);
                acc[r][0] = fma2(xd, w0, acc[r][0]);
                acc[r][1] = fma2(xd, w1, acc[r][1]);
                acc[r][2] = fma2(xd, w2, acc[r][2]);
                acc[r][3] = fma2(xd, w3, acc[r][3]);
            }
        }
    }

    {   // write y
        float* yb = y + ((size_t)(blk*64 + rbase))*128 + cbase;
        #pragma unroll
        for (int r = 0; r < 4; r++){
            float4 o0, o1;
            o0.x = lo2(acc[r][0]); o0.y = hi2(acc[r][0]);
            o0.z = lo2(acc[r][1]); o0.w = hi2(acc[r][1]);
            o1.x = lo2(acc[r][2]); o1.y = hi2(acc[r][2]);
            o1.z = lo2(acc[r][3]); o1.w = hi2(acc[r][3]);
            *(float4*)(yb + r*128)     = o0;
            *(float4*)(yb + r*128 + 4) = o1;
        }
    }

    // per-block column sum / sumsq -> smem -> global atomics
    ull s4[4] = {0,0,0,0}, q4[4] = {0,0,0,0};
    #pragma unroll
    for (int r = 0; r < 4; r++){
        #pragma unroll
        for (int q = 0; q < 4; q++){
            s4[q] = add2(s4[q], acc[r][q]);
            q4[q] = fma2(acc[r][q], acc[r][q], q4[q]);
        }
    }
    __syncthreads();
    float* ps = (float*)s_raw;        // [16][128]
    float* pq = ps + 16*128;
    #pragma unroll
    for (int q = 0; q < 4; q++){
        ps[tr*128 + cbase + 2*q]     = lo2(s4[q]);
        ps[tr*128 + cbase + 2*q + 1] = hi2(s4[q]);
        pq[tr*128 + cbase + 2*q]     = lo2(q4[q]);
        pq[tr*128 + cbase + 2*q + 1] = hi2(q4[q]);
    }
    __syncthreads();
    __shared__ unsigned s_last;
    if (t < 128){
        float ss = 0.f, qq = 0.f;
        #pragma unroll
        for (int i = 0; i < 16; i++){ ss += ps[i*128 + t]; qq += pq[i*128 + t]; }
        atomicAdd(&gs[t], ss);
        atomicAdd(&gq[t], qq);
    }
    __threadfence();
    __syncthreads();
    if (t == 0){
        const unsigned v = atomicInc(ctr, 511);   // wraps to 0 at old==511 (grid=512)
        s_last = (v == 511) ? 1u : 0u;
    }
    __syncthreads();
    if (s_last && t < 128){
        const float ss = atomicAdd(&gs[t], 0.f);  // coherent read
        const float qq = atomicAdd(&gq[t], 0.f);
        const float m  = ss * (1.f/32768.f);
        const float vv = qq * (1.f/32768.f) - m*m;
        const float sc = g[t] * rsqrtf(vv + 1e-5f);
        about[t]       = sc;
        about[128 + t] = be[t] - m*sc;
        gs[t] = 0.f;                              // reset for next gemm / next replay
        gq[t] = 0.f;
    }
}

// ---------------- final BN+ReLU to output ----------------
__global__ void __launch_bounds__(256,1) final_kernel(const float4* __restrict__ y,
                                                      const float* __restrict__ ab,
                                                      float4* __restrict__ out)
{
    const int i = blockIdx.x*256 + threadIdx.x;
    const int c = i & 31;
    const float4 sc = ((const float4*)ab)[c];
    const float4 sf = ((const float4*)ab)[32 + c];
    const float4 v = y[i];
    float4 o;
    o.x = fmaxf(fmaf(v.x, sc.x, sf.x), 0.f);
    o.y = fmaxf(fmaf(v.y, sc.y, sf.y), 0.f);
    o.z = fmaxf(fmaf(v.z, sc.z, sf.z), 0.f);
    o.w = fmaxf(fmaf(v.w, sc.w, sf.w), 0.f);
    out[i] = o;
}

// ---------------- launch ----------------
extern "C" void kernel_launch(void* const* d_in, const int* in_sizes, int n_in,
                              void* d_out, int out_size)
{
    const float* pos1  = (const float*)d_in[0];
    const float* pos2  = (const float*)d_in[1];
    const float* feat2 = (const float*)d_in[2];
    const float* Wm[3]  = {(const float*)d_in[3],  (const float*)d_in[7],  (const float*)d_in[11]};
    const float* bm[3]  = {(const float*)d_in[4],  (const float*)d_in[8],  (const float*)d_in[12]};
    const float* gm[3]  = {(const float*)d_in[5],  (const float*)d_in[9],  (const float*)d_in[13]};
    const float* bem[3] = {(const float*)d_in[6],  (const float*)d_in[10], (const float*)d_in[14]};

    float4 *wq, *pdist; int4 *iq, *pidx; float *x0, *ya, *yb, *gs, *gq, *ab, *wt;
    unsigned* ctr;
    cudaGetSymbolAddress((void**)&wq, g_wq);
    cudaGetSymbolAddress((void**)&iq, g_iq);
    cudaGetSymbolAddress((void**)&pdist, g_pd);
    cudaGetSymbolAddress((void**)&pidx, g_pi);
    cudaGetSymbolAddress((void**)&x0, g_x0);
    cudaGetSymbolAddress((void**)&ya, g_ya);
    cudaGetSymbolAddress((void**)&yb, g_yb);
    cudaGetSymbolAddress((void**)&gs, g_sum);
    cudaGetSymbolAddress((void**)&gq, g_sq);
    cudaGetSymbolAddress((void**)&ctr, g_ctr);
    cudaGetSymbolAddress((void**)&ab, g_ab);
    cudaGetSymbolAddress((void**)&wt, g_wt);
    float* wts[3] = {wt, wt + 16384, wt + 32768};

    const int gemm_smem = (64*132 + 128*128) * 4;
    cudaFuncSetAttribute(gemm_bn_kernel, cudaFuncAttributeMaxDynamicSharedMemorySize, gemm_smem);

    transpose3_kernel<<<192,256>>>(Wm[0], Wm[1], Wm[2], wt);

    knn_part_kernel<<<(Nq/KQB)*NCH, KTPB>>>(pos1, pos2, pdist, pidx);
    knn_merge_kernel<<<Nq/256, 256>>>(pos1, pdist, pidx, wq, iq);
    interp_kernel<<<4096,256>>>(feat2, wq, iq, x0);

    gemm_bn_kernel<<<512,256,gemm_smem>>>(x0, wts[0], bm[0], 0,  gm[0], bem[0], ya, gs, gq, ctr, ab);
    gemm_bn_kernel<<<512,256,gemm_smem>>>(ya, wts[1], bm[1], ab, gm[1], bem[1], yb, gs, gq, ctr, ab);
    gemm_bn_kernel<<<512,256,gemm_smem>>>(yb, wts[2], bm[2], ab, gm[2], bem[2], x0, gs, gq, ctr, ab);
    final_kernel<<<4096,256>>>((const float4*)x0, ab, (float4*)d_out);
}

// round 6
// speedup vs baseline: 1.1703x; 1.1703x over previous
#include <cuda_runtime.h>

#define Nq 32768
#define Mp 8192
#define C  128

// ---- knn config ----
#define KTPB 128            // threads per knn block
#define KQB  128            // queries per block (QPT=1)
#define NCH  4              // candidate quarters
#define KHALF (Mp/NCH)      // 2048 candidates per chunk
#define SUB  512            // pairs per smem sub-chunk (16KB)
#define NSUB (KHALF/2/SUB)  // 2 sub-chunks per chunk

typedef unsigned long long ull;

union F2U { float2 f; ull u; };
__device__ __forceinline__ ull pk2(float a, float b){ F2U t; t.f.x=a; t.f.y=b; return t.u; }
__device__ __forceinline__ float lo2(ull v){ F2U t; t.u=v; return t.f.x; }
__device__ __forceinline__ float hi2(ull v){ F2U t; t.u=v; return t.f.y; }
__device__ __forceinline__ ull fma2(ull a, ull b, ull c){
    ull d; asm("fma.rn.f32x2 %0, %1, %2, %3;" : "=l"(d) : "l"(a), "l"(b), "l"(c)); return d;
}
__device__ __forceinline__ ull add2(ull a, ull b){
    ull d; asm("add.rn.f32x2 %0, %1, %2;" : "=l"(d) : "l"(a), "l"(b)); return d;
}

// branchless stable top-3 insert (strict <  => ties keep earlier/lower index)
__device__ __forceinline__ void ins3(float t, int idx,
                                     float& d0, float& d1, float& d2,
                                     int& i0, int& i1, int& i2)
{
    const bool c0 = t < d0, c1 = t < d1, c2 = t < d2;
    d2 = c1 ? d1 : (c2 ? t : d2);
    i2 = c1 ? i1 : (c2 ? idx : i2);
    d1 = c0 ? d0 : (c1 ? t : d1);
    i1 = c0 ? i0 : (c1 ? idx : i1);
    d0 = c0 ? t : d0;
    i0 = c0 ? idx : i0;
}

// ---------------- scratch (device globals; no allocs allowed) ----------------
__device__ float4 g_wq[Nq];
__device__ int4   g_iq[Nq];
__device__ float4 g_pd[NCH*Nq];
__device__ int4   g_pi[NCH*Nq];
__device__ float  g_x0[Nq*C];
__device__ float  g_ya[Nq*C];
__device__ float  g_yb[Nq*C];
__device__ float  g_wt[3*C*C];
__device__ float  g_sum[C];
__device__ float  g_sq[C];
__device__ unsigned g_ctr;
__device__ float  g_ab[2*C];

extern __shared__ unsigned char s_raw[];

// ---------------- W transpose x3 in one launch ----------------
__global__ void __launch_bounds__(256,1) transpose3_kernel(const float* __restrict__ w0,
                                                           const float* __restrict__ w1,
                                                           const float* __restrict__ w2,
                                                           float* __restrict__ wt)
{
    const int b = blockIdx.x;                  // 192 blocks
    const float* w = (b < 64) ? w0 : ((b < 128) ? w1 : w2);
    const int local = (b & 63)*256 + threadIdx.x;   // 0..16383
    wt[(b >> 6)*16384 + local] = w[(local & 127)*128 + (local >> 7)];
}

// -------- kNN partial: QPT=1, streamed smem sub-chunks, branchless insert --------
__global__ void __launch_bounds__(KTPB,8) knn_part_kernel(const float* __restrict__ pos1,
                                                          const float* __restrict__ pos2,
                                                          float4* __restrict__ pd,
                                                          int4*  __restrict__ pi)
{
    __shared__ ulonglong2 sA[SUB];   // (.x = x-pair, .y = y-pair) of (-2x)
    __shared__ ulonglong2 sB[SUB];   // (.x = z-pair, .y = n2-pair)
    const int t     = threadIdx.x;
    const int chunk = blockIdx.x & (NCH-1);
    const int n     = (blockIdx.x >> 2) * KQB + t;   // this thread's query

    const float px = pos1[3*n], py = pos1[3*n+1], pz = pos1[3*n+2];
    const ull pxx = pk2(px,px), pyy = pk2(py,py), pzz = pk2(pz,pz);

    float d0=3.4e38f, d1=3.4e38f, d2=3.4e38f;
    int   i0=0, i1=0, i2=0;

    const int pb0 = chunk * (KHALF/2);   // base pair index for this chunk

    for (int sc = 0; sc < NSUB; sc++){
        const int pb = pb0 + sc*SUB;
        __syncthreads();
        #pragma unroll
        for (int i = 0; i < SUB/KTPB; i++){          // 4 pair-loads per thread
            const int p = t + i*KTPB;
            const float2* q2 = (const float2*)(pos2 + 6*(pb + p));
            const float2 a = q2[0], b = q2[1], c = q2[2];
            const float x0=a.x, y0=a.y, z0=b.x, x1=b.y, y1=c.x, z1=c.y;
            const float n0 = x0*x0 + y0*y0 + z0*z0;
            const float n1 = x1*x1 + y1*y1 + z1*z1;
            ulonglong2 A, B;
            A.x = pk2(-2.f*x0, -2.f*x1);
            A.y = pk2(-2.f*y0, -2.f*y1);
            B.x = pk2(-2.f*z0, -2.f*z1);
            B.y = pk2(n0, n1);
            sA[p] = A; sB[p] = B;
        }
        __syncthreads();

        #pragma unroll 4
        for (int p = 0; p < SUB; p++){
            const ulonglong2 A = sA[p];
            const ulonglong2 B = sB[p];
            ull tt = fma2(pzz, B.x, B.y);
            tt = fma2(pyy, A.y, tt);
            tt = fma2(pxx, A.x, tt);
            const float tl = lo2(tt), th = hi2(tt);
            if (fminf(tl, th) < d2){
                const int g = 2*(pb + p);
                ins3(tl, g,   d0, d1, d2, i0, i1, i2);
                ins3(th, g+1, d0, d1, d2, i0, i1, i2);
            }
        }
    }

    pd[chunk*Nq + n] = make_float4(d0, d1, d2, 0.f);
    pi[chunk*Nq + n] = make_int4(i0, i1, i2, 0);
}

// ---------------- merge partials -> weights/indices ----------------
__global__ void __launch_bounds__(256,1) knn_merge_kernel(const float* __restrict__ pos1,
                                                          const float4* __restrict__ pd,
                                                          const int4*  __restrict__ pi,
                                                          float4* __restrict__ wq,
                                                          int4*  __restrict__ iq)
{
    const int n = blockIdx.x*256 + threadIdx.x;
    float4 v = pd[n];
    int4  id = pi[n];
    float d0=v.x, d1=v.y, d2=v.z;
    int   i0=id.x, i1=id.y, i2=id.z;

    #pragma unroll
    for (int c = 1; c < NCH; c++){
        const float4 e = pd[c*Nq + n];
        const int4   j = pi[c*Nq + n];
        ins3(e.x, j.x, d0, d1, d2, i0, i1, i2);
        ins3(e.y, j.y, d0, d1, d2, i0, i1, i2);
        ins3(e.z, j.z, d0, d1, d2, i0, i1, i2);
    }

    const float px = pos1[3*n], py = pos1[3*n+1], pz = pos1[3*n+2];
    const float n1 = px*px + py*py + pz*pz;
    const float a0 = fmaxf(d0 + n1, 0.f) + 1e-8f;
    const float a1 = fmaxf(d1 + n1, 0.f) + 1e-8f;
    const float a2 = fmaxf(d2 + n1, 0.f) + 1e-8f;
    const float w0 = 1.f/a0, w1 = 1.f/a1, w2 = 1.f/a2;
    const float inv = 1.f/(w0 + w1 + w2);
    wq[n] = make_float4(w0*inv, w1*inv, w2*inv, 0.f);
    iq[n] = make_int4(i0, i1, i2, 0);
}

// ---------------- interpolation: warp per point ----------------
__global__ void __launch_bounds__(256,1) interp_kernel(const float* __restrict__ feat2,
                                                       const float4* __restrict__ wq,
                                                       const int4*  __restrict__ iq,
                                                       float* __restrict__ x0)
{
    const int gw   = (blockIdx.x*256 + threadIdx.x) >> 5;
    const int lane = threadIdx.x & 31;
    const int4   id = iq[gw];
    const float4 w  = wq[gw];
    const float4* f4 = (const float4*)feat2;
    const float4 a = f4[id.x*32 + lane];
    const float4 b = f4[id.y*32 + lane];
    const float4 c = f4[id.z*32 + lane];
    float4 o;
    o.x = a.x*w.x + b.x*w.y + c.x*w.z;
    o.y = a.y*w.x + b.y*w.y + c.y*w.z;
    o.z = a.z*w.x + b.z*w.y + c.z*w.z;
    o.w = a.w*w.x + b.w*w.y + c.w*w.z;
    ((float4*)x0)[gw*32 + lane] = o;
}

// -- fused GEMM (+prev BN/ReLU on load) + BN-stat accumulation + last-block stats --
// 128x128 tile, 256 threads, 8x8 micro-tile (R4-proven config)
__global__ void __launch_bounds__(256,1) gemm_bn_kernel(const float* __restrict__ x,
                                                        const float* __restrict__ wt,   // [k][j]
                                                        const float* __restrict__ bias,
                                                        const float* __restrict__ abin, // prev scale|shift or null
                                                        const float* __restrict__ g,
                                                        const float* __restrict__ be,
                                                        float* __restrict__ y,
                                                        float* __restrict__ gs,
                                                        float* __restrict__ gq,
                                                        unsigned* __restrict__ ctr,
                                                        float* __restrict__ about)
{
    float* Xs = (float*)s_raw;        // [128][132]
    float* Ws = Xs + 128*132;         // [128][128]
    const int t   = threadIdx.x;
    const int blk = blockIdx.x;

    {
        const float4* wt4 = (const float4*)wt;
        float4* ws4 = (float4*)Ws;
        #pragma unroll
        for (int i = 0; i < 16; i++) ws4[i*256 + t] = wt4[i*256 + t];
    }
    {
        const int lane = t & 31;
        const int rg   = t >> 5;
        float4 sc, sf;
        const bool aff = (abin != 0);
        if (aff){ sc = ((const float4*)abin)[lane]; sf = ((const float4*)abin)[32 + lane]; }
        const float4* x4 = (const float4*)x + (size_t)blk*(128*32);
        #pragma unroll
        for (int i = 0; i < 16; i++){
            const int r = rg + i*8;
            float4 v = x4[r*32 + lane];
            if (aff){
                v.x = fmaxf(fmaf(v.x, sc.x, sf.x), 0.f);
                v.y = fmaxf(fmaf(v.y, sc.y, sf.y), 0.f);
                v.z = fmaxf(fmaf(v.z, sc.z, sf.z), 0.f);
                v.w = fmaxf(fmaf(v.w, sc.w, sf.w), 0.f);
            }
            *(float4*)(Xs + r*132 + lane*4) = v;
        }
    }
    __syncthreads();

    const int tc = t & 15, tr = t >> 4;
    const int rbase = tr*8, cbase = tc*8;

    ull acc[8][4];
    {
        const ull b0 = pk2(bias[cbase+0], bias[cbase+1]);
        const ull b1 = pk2(bias[cbase+2], bias[cbase+3]);
        const ull b2 = pk2(bias[cbase+4], bias[cbase+5]);
        const ull b3 = pk2(bias[cbase+6], bias[cbase+7]);
        #pragma unroll
        for (int r = 0; r < 8; r++){ acc[r][0]=b0; acc[r][1]=b1; acc[r][2]=b2; acc[r][3]=b3; }
    }

    const float* xrow = Xs + rbase*132;
    #pragma unroll 4
    for (int k = 0; k < 128; k++){
        const float4 wa = *(const float4*)(Ws + k*128 + cbase);
        const float4 wb = *(const float4*)(Ws + k*128 + cbase + 4);
        const ull w0 = pk2(wa.x, wa.y), w1 = pk2(wa.z, wa.w);
        const ull w2 = pk2(wb.x, wb.y), w3 = pk2(wb.z, wb.w);
        #pragma unroll
        for (int r = 0; r < 8; r++){
            const float xv = xrow[r*132 + k];
            const ull xd = pk2(xv, xv);
            acc[r][0] = fma2(xd, w0, acc[r][0]);
            acc[r][1] = fma2(xd, w1, acc[r][1]);
            acc[r][2] = fma2(xd, w2, acc[r][2]);
            acc[r][3] = fma2(xd, w3, acc[r][3]);
        }
    }

    {
        float* yb = y + ((size_t)(blk*128 + rbase))*128 + cbase;
        #pragma unroll
        for (int r = 0; r < 8; r++){
            float4 o0, o1;
            o0.x = lo2(acc[r][0]); o0.y = hi2(acc[r][0]);
            o0.z = lo2(acc[r][1]); o0.w = hi2(acc[r][1]);
            o1.x = lo2(acc[r][2]); o1.y = hi2(acc[r][2]);
            o1.z = lo2(acc[r][3]); o1.w = hi2(acc[r][3]);
            *(float4*)(yb + r*128)     = o0;
            *(float4*)(yb + r*128 + 4) = o1;
        }
    }

    // per-block column sum / sumsq -> smem -> global atomics
    ull s4[4] = {0,0,0,0}, q4[4] = {0,0,0,0};
    #pragma unroll
    for (int r = 0; r < 8; r++){
        #pragma unroll
        for (int q = 0; q < 4; q++){
            s4[q] = add2(s4[q], acc[r][q]);
            q4[q] = fma2(acc[r][q], acc[r][q], q4[q]);
        }
    }
    __syncthreads();
    float* ps = (float*)s_raw;
    float* pq = ps + 16*128;
    #pragma unroll
    for (int q = 0; q < 4; q++){
        ps[tr*128 + cbase + 2*q]     = lo2(s4[q]);
        ps[tr*128 + cbase + 2*q + 1] = hi2(s4[q]);
        pq[tr*128 + cbase + 2*q]     = lo2(q4[q]);
        pq[tr*128 + cbase + 2*q + 1] = hi2(q4[q]);
    }
    __syncthreads();
    __shared__ unsigned s_last;
    if (t < 128){
        float ss = 0.f, qq = 0.f;
        #pragma unroll
        for (int i = 0; i < 16; i++){ ss += ps[i*128 + t]; qq += pq[i*128 + t]; }
        atomicAdd(&gs[t], ss);
        atomicAdd(&gq[t], qq);
    }
    __threadfence();
    __syncthreads();
    if (t == 0){
        const unsigned v = atomicInc(ctr, 255);   // wraps to 0 at old==255 (grid=256)
        s_last = (v == 255) ? 1u : 0u;
    }
    __syncthreads();
    if (s_last && t < 128){
        const float ss = atomicAdd(&gs[t], 0.f);  // coherent read
        const float qq = atomicAdd(&gq[t], 0.f);
        const float m  = ss * (1.f/32768.f);
        const float vv = qq * (1.f/32768.f) - m*m;
        const float sc = g[t] * rsqrtf(vv + 1e-5f);
        about[t]       = sc;
        about[128 + t] = be[t] - m*sc;
        gs[t] = 0.f;                              // reset for next gemm / next replay
        gq[t] = 0.f;
    }
}

// ---------------- final BN+ReLU to output ----------------
__global__ void __launch_bounds__(256,1) final_kernel(const float4* __restrict__ y,
                                                      const float* __restrict__ ab,
                                                      float4* __restrict__ out)
{
    const int i = blockIdx.x*256 + threadIdx.x;
    const int c = i & 31;
    const float4 sc = ((const float4*)ab)[c];
    const float4 sf = ((const float4*)ab)[32 + c];
    const float4 v = y[i];
    float4 o;
    o.x = fmaxf(fmaf(v.x, sc.x, sf.x), 0.f);
    o.y = fmaxf(fmaf(v.y, sc.y, sf.y), 0.f);
    o.z = fmaxf(fmaf(v.z, sc.z, sf.z), 0.f);
    o.w = fmaxf(fmaf(v.w, sc.w, sf.w), 0.f);
    out[i] = o;
}

// ---------------- launch ----------------
extern "C" void kernel_launch(void* const* d_in, const int* in_sizes, int n_in,
                              void* d_out, int out_size)
{
    const float* pos1  = (const float*)d_in[0];
    const float* pos2  = (const float*)d_in[1];
    const float* feat2 = (const float*)d_in[2];
    const float* Wm[3]  = {(const float*)d_in[3],  (const float*)d_in[7],  (const float*)d_in[11]};
    const float* bm[3]  = {(const float*)d_in[4],  (const float*)d_in[8],  (const float*)d_in[12]};
    const float* gm[3]  = {(const float*)d_in[5],  (const float*)d_in[9],  (const float*)d_in[13]};
    const float* bem[3] = {(const float*)d_in[6],  (const float*)d_in[10], (const float*)d_in[14]};

    float4 *wq, *pdist; int4 *iq, *pidx; float *x0, *ya, *yb, *gs, *gq, *ab, *wt;
    unsigned* ctr;
    cudaGetSymbolAddress((void**)&wq, g_wq);
    cudaGetSymbolAddress((void**)&iq, g_iq);
    cudaGetSymbolAddress((void**)&pdist, g_pd);
    cudaGetSymbolAddress((void**)&pidx, g_pi);
    cudaGetSymbolAddress((void**)&x0, g_x0);
    cudaGetSymbolAddress((void**)&ya, g_ya);
    cudaGetSymbolAddress((void**)&yb, g_yb);
    cudaGetSymbolAddress((void**)&gs, g_sum);
    cudaGetSymbolAddress((void**)&gq, g_sq);
    cudaGetSymbolAddress((void**)&ctr, g_ctr);
    cudaGetSymbolAddress((void**)&ab, g_ab);
    cudaGetSymbolAddress((void**)&wt, g_wt);
    float* wts[3] = {wt, wt + 16384, wt + 32768};

    const int gemm_smem = (128*132 + 128*128) * 4;
    cudaFuncSetAttribute(gemm_bn_kernel, cudaFuncAttributeMaxDynamicSharedMemorySize, gemm_smem);

    transpose3_kernel<<<192,256>>>(Wm[0], Wm[1], Wm[2], wt);

    knn_part_kernel<<<(Nq/KQB)*NCH, KTPB>>>(pos1, pos2, pdist, pidx);
    knn_merge_kernel<<<Nq/256, 256>>>(pos1, pdist, pidx, wq, iq);
    interp_kernel<<<4096,256>>>(feat2, wq, iq, x0);

    gemm_bn_kernel<<<256,256,gemm_smem>>>(x0, wts[0], bm[0], 0,  gm[0], bem[0], ya, gs, gq, ctr, ab);
    gemm_bn_kernel<<<256,256,gemm_smem>>>(ya, wts[1], bm[1], ab, gm[1], bem[1], yb, gs, gq, ctr, ab);
    gemm_bn_kernel<<<256,256,gemm_smem>>>(yb, wts[2], bm[2], ab, gm[2], bem[2], x0, gs, gq, ctr, ab);
    final_kernel<<<4096,256>>>((const float4*)x0, ab, (float4*)d_out);
}